// round 7
// baseline (speedup 1.0000x reference)
#include <cuda_runtime.h>
#include <math.h>

// Problem constants (fixed shapes)
#define B_ROWS  65536
#define D_DIM   256
#define L_LVL   4
#define K_CODES 2048

// GEMM tiling: 128x128 tile, 256 threads, 8x8 microtile (FFMA2 col pairs), BK=16
#define BM 128
#define BN 128
#define BK 16
#define NTHREADS 256
#define NT_TILES (K_CODES / BN)   // 16
#define NCHUNK   (D_DIM / BK)     // 16
#define NTILES_TOTAL (B_ROWS / BM)  // 512
#define GRID_PERSIST 296            // 148 SMs x 2 CTAs

// Scratch (allocation-free rule: __device__ globals)
__device__ float g_res[(size_t)B_ROWS * D_DIM];   // running residual, 64 MB
__device__ float g_e2[L_LVL * K_CODES];           // per-code squared norms
__device__ int   g_ctr[L_LVL];                    // per-level tile queue

// Packed fp32 (sm_100+): 2 IEEE fp32 FMAs per instruction
#define PACK_DUP(d, s) asm("mov.b64 %0, {%1, %1};" : "=l"(d) : "f"(s))
#define FMA2(acc, a, b) asm("fma.rn.f32x2 %0, %1, %2, %0;" : "+l"(acc) : "l"(a), "l"(b))
#define UNPACK2(lo, hi, v) asm("mov.b64 {%0, %1}, %2;" : "=f"(lo), "=f"(hi) : "l"(v))

// ---------------------------------------------------------------------------
// e2[l*K + k] = sum_d codebooks[l,k,d]^2  in fp64 -> fp32. Also resets the
// per-level tile counters (runs before any level kernel on every replay).
// ---------------------------------------------------------------------------
__global__ void e2_kernel(const float* __restrict__ codebooks)
{
    if (blockIdx.x == 0 && threadIdx.x < L_LVL) g_ctr[threadIdx.x] = 0;
    int warp = (blockIdx.x * blockDim.x + threadIdx.x) >> 5;
    int lane = threadIdx.x & 31;
    if (warp >= L_LVL * K_CODES) return;
    const float* p = codebooks + (size_t)warp * D_DIM;
    double s = 0.0;
    #pragma unroll
    for (int i = 0; i < D_DIM / 32; ++i) {
        double v = (double)p[lane + 32 * i];
        s += v * v;
    }
    #pragma unroll
    for (int o = 16; o; o >>= 1) s += __shfl_xor_sync(0xffffffffu, s, o);
    if (lane == 0) g_e2[warp] = (float)s;
}

// ---------------------------------------------------------------------------
// One RQ level, persistent-CTA version. Score chain matches the reference
// rounding exactly: S = fl( fl(x2 + e2[k]) - 2*dot ), fp32 fma chain,
// ascending k; ties break to lower index (jnp.argmin first occurrence).
// A is staged in smem as duplicated {v,v} 64-bit pairs so FFMA2's broadcast
// operand comes straight from LDS (no per-kk MOV dup).
// ---------------------------------------------------------------------------
__global__ __launch_bounds__(NTHREADS, 2)
void rq_level_kernel(const float* __restrict__ residual,   // original input [B,D]
                     const float* __restrict__ codebooks,  // [L,K,D]
                     float* __restrict__ quant,            // [B,D] running qsum (d_out)
                     float* __restrict__ codes_out,        // [B,L] as float
                     int level)
{
    // A dup: pair for col c at floats [2c, 2c+1]; row pitch 2*BM+4 = 260 floats
    // (1040B: 16B-aligned rows, STS.64 only 2-way conflicted).
    __shared__ __align__(16) float Asd[2][BK][2 * BM + 4];
    __shared__ __align__(16) float Bs[2][BK][BN + 4];
    __shared__ float redV[BM][16];
    __shared__ int   redI[BM][16];
    __shared__ float sh_x2[BM];
    __shared__ int   sh_tile;

    const float* res_in  = (level == 0) ? residual : g_res;
    float*       res_out = g_res;
    const float* emb = codebooks + (size_t)level * K_CODES * D_DIM;
    const float* e2  = g_e2 + level * K_CODES;

    const int tid  = threadIdx.x;
    const int nIdx = tid & 15;          // cols {nIdx*4..+3} U {64+nIdx*4..+3}
    const int mIdx = tid >> 4;          // rows {mIdx*4..+3} U {64+mIdx*4..+3}

    const int ldd = tid & 15;           // d within BK chunk for tile loads
    const int ldr = tid >> 4;           // base row for tile loads (0..15)

    while (true) {
        __syncthreads();                 // protect sh_tile + smem reuse
        if (tid == 0) sh_tile = atomicAdd(&g_ctr[level], 1);
        __syncthreads();
        const int tile = sh_tile;
        if (tile >= NTILES_TOTAL) break;
        const int bm = tile * BM;

        // ---- per-row x2 = sum(res^2) in fp64 -> fp32 (2 threads per row) ----
        {
            int r = tid >> 1;
            int h = tid & 1;
            const float* p = res_in + (size_t)(bm + r) * D_DIM + h * 128;
            double s0 = 0.0, s1 = 0.0;
            #pragma unroll 16
            for (int i = 0; i < 128; i += 2) {
                double v0 = (double)p[i], v1 = (double)p[i + 1];
                s0 += v0 * v0; s1 += v1 * v1;
            }
            double s = s0 + s1;
            s += __shfl_xor_sync(0xffffffffu, s, 1);
            if (h == 0) sh_x2[r] = (float)s;
        }
        __syncthreads();

        float minV[8];
        int   minI[8];
        #pragma unroll
        for (int i = 0; i < 8; ++i) { minV[i] = INFINITY; minI[i] = 0; }

        const float* aG = res_in + (size_t)bm * D_DIM;

        for (int nt = 0; nt < NT_TILES; ++nt) {
            const float* bG = emb + (size_t)(nt * BN) * D_DIM;

            // acc2[i][j]: j=0,1 -> cols (nIdx*4+0,1),(nIdx*4+2,3)
            //             j=2,3 -> 64+ same
            unsigned long long acc2[8][4];
            #pragma unroll
            for (int i = 0; i < 8; ++i)
                #pragma unroll
                for (int j = 0; j < 4; ++j) acc2[i][j] = 0ull;

            float ra[8], rb[8];
            // prologue: fetch + store chunk 0
            #pragma unroll
            for (int i = 0; i < 8; ++i) {
                int r = ldr + 16 * i;
                ra[i] = aG[(size_t)r * D_DIM + ldd];
                rb[i] = bG[(size_t)r * D_DIM + ldd];
            }
            #pragma unroll
            for (int i = 0; i < 8; ++i) {
                int r = ldr + 16 * i;
                unsigned long long pv; PACK_DUP(pv, ra[i]);
                *(unsigned long long*)&Asd[0][ldd][2 * r] = pv;
                Bs[0][ldd][r] = rb[i];
            }
            __syncthreads();

            #pragma unroll 2
            for (int c = 0; c < NCHUNK; ++c) {
                const int cur = c & 1;
                if (c < NCHUNK - 1) {
                    int dc = (c + 1) * BK;
                    #pragma unroll
                    for (int i = 0; i < 8; ++i) {
                        int r = ldr + 16 * i;
                        ra[i] = aG[(size_t)r * D_DIM + dc + ldd];
                        rb[i] = bG[(size_t)r * D_DIM + dc + ldd];
                    }
                }
                #pragma unroll 8
                for (int kk = 0; kk < BK; ++kk) {
                    // dup-A pairs straight from LDS.128 (broadcast, conflict-free)
                    const ulonglong2 aq0 = *(const ulonglong2*)(&Asd[cur][kk][2 * (mIdx * 4)]);
                    const ulonglong2 aq1 = *(const ulonglong2*)(&Asd[cur][kk][2 * (mIdx * 4 + 2)]);
                    const ulonglong2 aq2 = *(const ulonglong2*)(&Asd[cur][kk][2 * (64 + mIdx * 4)]);
                    const ulonglong2 aq3 = *(const ulonglong2*)(&Asd[cur][kk][2 * (64 + mIdx * 4 + 2)]);
                    const ulonglong2 b0  = *(const ulonglong2*)(&Bs[cur][kk][nIdx * 4]);
                    const ulonglong2 b1  = *(const ulonglong2*)(&Bs[cur][kk][64 + nIdx * 4]);
                    const unsigned long long aD[8] =
                        { aq0.x, aq0.y, aq1.x, aq1.y, aq2.x, aq2.y, aq3.x, aq3.y };
                    const unsigned long long bP[4] = { b0.x, b0.y, b1.x, b1.y };
                    #pragma unroll
                    for (int i = 0; i < 8; ++i)
                        #pragma unroll
                        for (int j = 0; j < 4; ++j)
                            FMA2(acc2[i][j], aD[i], bP[j]);
                }
                if (c < NCHUNK - 1) {
                    const int nxt = (c + 1) & 1;
                    #pragma unroll
                    for (int i = 0; i < 8; ++i) {
                        int r = ldr + 16 * i;
                        unsigned long long pv; PACK_DUP(pv, ra[i]);
                        *(unsigned long long*)&Asd[nxt][ldd][2 * r] = pv;
                        Bs[nxt][ldd][r] = rb[i];
                    }
                }
                __syncthreads();
            }

            // epilogue: S = fl(fl(x2 + e2[k]) - 2*dot); running argmin, ascending k
            #pragma unroll
            for (int j = 0; j < 4; ++j) {
                int c0 = (j < 2) ? (nIdx * 4 + 2 * j) : (64 + nIdx * 4 + 2 * (j - 2));
                int g0 = nt * BN + c0;
                float ek0 = __ldg(&e2[g0]);
                float ek1 = __ldg(&e2[g0 + 1]);
                #pragma unroll
                for (int i = 0; i < 8; ++i) {
                    int r = (i < 4) ? (mIdx * 4 + i) : (64 + mIdx * 4 + (i - 4));
                    float x2r = sh_x2[r];
                    float dlo, dhi;
                    UNPACK2(dlo, dhi, acc2[i][j]);
                    float A0 = __fadd_rn(x2r, ek0);
                    float s0 = __fmaf_rn(-2.0f, dlo, A0);
                    if (s0 < minV[i]) { minV[i] = s0; minI[i] = g0; }
                    float A1 = __fadd_rn(x2r, ek1);
                    float s1 = __fmaf_rn(-2.0f, dhi, A1);
                    if (s1 < minV[i]) { minV[i] = s1; minI[i] = g0 + 1; }
                }
            }
        }

        // cross-thread argmin reduction (16 candidates per row), lexicographic
        __syncthreads();
        #pragma unroll
        for (int i = 0; i < 8; ++i) {
            int r = (i < 4) ? (mIdx * 4 + i) : (64 + mIdx * 4 + (i - 4));
            redV[r][nIdx] = minV[i];
            redI[r][nIdx] = minI[i];
        }
        __syncthreads();

        if (tid < BM) {
            float bv = redV[tid][0];
            int   bi = redI[tid][0];
            #pragma unroll
            for (int j = 1; j < 16; ++j) {
                float v = redV[tid][j];
                int  ix = redI[tid][j];
                if (v < bv || (v == bv && ix < bi)) { bv = v; bi = ix; }
            }
            redI[tid][0] = bi;
            codes_out[(size_t)(bm + tid) * L_LVL + level] = (float)bi;
        }
        __syncthreads();

        // residual update + qsum accumulation, coalesced (float4 granularity)
        #pragma unroll
        for (int it = 0; it < (BM * D_DIM / 4) / NTHREADS; ++it) {
            int f  = tid + NTHREADS * it;
            int r  = f >> 6;                   // 64 float4 per row
            int d4 = f & 63;
            int q  = redI[r][0];
            size_t off = (size_t)(bm + r) * D_DIM + d4 * 4;
            float4 a = *(const float4*)(res_in + off);
            float4 e = *(const float4*)(emb + (size_t)q * D_DIM + d4 * 4);
            *(float4*)(res_out + off) =
                make_float4(__fadd_rn(a.x, -e.x), __fadd_rn(a.y, -e.y),
                            __fadd_rn(a.z, -e.z), __fadd_rn(a.w, -e.w));
            if (level == 0) {
                *(float4*)(quant + off) = e;   // qsum = fl(0 + q) = q
            } else {
                float4 p = *(const float4*)(quant + off);
                *(float4*)(quant + off) =
                    make_float4(__fadd_rn(p.x, e.x), __fadd_rn(p.y, e.y),
                                __fadd_rn(p.z, e.z), __fadd_rn(p.w, e.w));
            }
        }
    }
}

// ---------------------------------------------------------------------------
extern "C" void kernel_launch(void* const* d_in, const int* in_sizes, int n_in,
                              void* d_out, int out_size)
{
    const float* residual  = (const float*)d_in[0];   // [B, D] float32
    const float* codebooks = (const float*)d_in[1];   // [L, K, D] float32
    float* out   = (float*)d_out;
    float* quant = out;                               // [B, D]
    float* codes = out + (size_t)B_ROWS * D_DIM;      // [B, L] as float

    e2_kernel<<<(L_LVL * K_CODES * 32 + 255) / 256, 256>>>(codebooks);

    for (int l = 0; l < L_LVL; ++l)
        rq_level_kernel<<<GRID_PERSIST, NTHREADS>>>(residual, codebooks, quant, codes, l);
}

// round 13
// speedup vs baseline: 1.7126x; 1.7126x over previous
#include <cuda_runtime.h>
#include <math.h>

// Problem constants (fixed shapes)
#define B_ROWS  65536
#define D_DIM   256
#define L_LVL   4
#define K_CODES 2048

// GEMM tiling: 128 rows x 512 codes per CTA, 256 threads, 8x8 microtile, BK=16
#define BM 128
#define BN 128
#define BK 16
#define NTHREADS 256
#define NQ 4                       // codebook quarters (one per CTA)
#define QN (K_CODES / NQ)          // 512 codes per quarter
#define NT_TILES (QN / BN)         // 4
#define NCHUNK   (D_DIM / BK)      // 16
#define NROWTILES (B_ROWS / BM)    // 512

// Scratch (allocation-free rule: __device__ globals)
__device__ float g_res[(size_t)B_ROWS * D_DIM];   // running residual, 64 MB
__device__ float g_e2[L_LVL * K_CODES];           // per-code squared norms
__device__ float g_x2[B_ROWS];                    // per-row squared norms (current level)
__device__ float g_bv[NQ * B_ROWS];               // per-quarter best score
__device__ int   g_bi[NQ * B_ROWS];               // per-quarter best index

// Packed fp32 (sm_100+): 2 IEEE fp32 FMAs per instruction (halves issue count)
#define PACK_DUP(d, s) asm("mov.b64 %0, {%1, %1};" : "=l"(d) : "f"(s))
#define FMA2(acc, a, b) asm("fma.rn.f32x2 %0, %1, %2, %0;" : "+l"(acc) : "l"(a), "l"(b))
#define UNPACK2(lo, hi, v) asm("mov.b64 {%0, %1}, %2;" : "=f"(lo), "=f"(hi) : "l"(v))

// ---------------------------------------------------------------------------
// e2[l*K + k] = sum_d codebooks[l,k,d]^2  in fp64 -> fp32.
// ---------------------------------------------------------------------------
__global__ void e2_kernel(const float* __restrict__ codebooks)
{
    int warp = (blockIdx.x * blockDim.x + threadIdx.x) >> 5;
    int lane = threadIdx.x & 31;
    if (warp >= L_LVL * K_CODES) return;
    const float* p = codebooks + (size_t)warp * D_DIM;
    double s = 0.0;
    #pragma unroll
    for (int i = 0; i < D_DIM / 32; ++i) {
        double v = (double)p[lane + 32 * i];
        s += v * v;
    }
    #pragma unroll
    for (int o = 16; o; o >>= 1) s += __shfl_xor_sync(0xffffffffu, s, o);
    if (lane == 0) g_e2[warp] = (float)s;
}

// ---------------------------------------------------------------------------
// g_x2[row] = sum_d residual[row,d]^2 in fp64 -> fp32 (level 0 only).
// Block = 32 rows, 8 threads per row.
// ---------------------------------------------------------------------------
__global__ void x2_kernel(const float* __restrict__ src)
{
    int t = threadIdx.x;
    int row = blockIdx.x * 32 + (t >> 3);
    int lane8 = t & 7;
    const float4* p = (const float4*)(src + (size_t)row * D_DIM);
    double s = 0.0;
    #pragma unroll
    for (int j = 0; j < 8; ++j) {
        float4 v = p[lane8 + 8 * j];
        s += (double)v.x * v.x + (double)v.y * v.y
           + (double)v.z * v.z + (double)v.w * v.w;
    }
    s += __shfl_xor_sync(0xffffffffu, s, 4);
    s += __shfl_xor_sync(0xffffffffu, s, 2);
    s += __shfl_xor_sync(0xffffffffu, s, 1);
    if (lane8 == 0) g_x2[row] = (float)s;
}

// ---------------------------------------------------------------------------
// One RQ level, one codebook-quarter per CTA (2048 CTAs -> ~7 tiles/slot,
// 98.8% wave balance). Score chain matches the reference rounding exactly:
//   S = fl( fl(x2 + e2[k]) - 2*dot ), fp32 fma chain, ascending k.
// Writes per-quarter (best score, best index) to global.
// ---------------------------------------------------------------------------
__global__ __launch_bounds__(NTHREADS, 2)
void rq_level_kernel(const float* __restrict__ residual,   // original input [B,D]
                     const float* __restrict__ codebooks,  // [L,K,D]
                     int level)
{
    __shared__ float As[2][BK][BM + 4];   // res chunk, K-major, double-buffered
    __shared__ float Bs[2][BK][BN + 4];   // emb chunk, K-major, double-buffered
    __shared__ float redV[BM][16];
    __shared__ int   redI[BM][16];
    __shared__ float sh_x2[BM];

    const float* res_in = (level == 0) ? residual : g_res;
    const float* emb = codebooks + (size_t)level * K_CODES * D_DIM;
    const float* e2  = g_e2 + level * K_CODES;

    const int quarter = blockIdx.x & (NQ - 1);
    const int bm      = (blockIdx.x >> 2) * BM;

    const int tid  = threadIdx.x;
    const int nIdx = tid & 15;          // cols {nIdx*4..+3} U {64+nIdx*4..+3}
    const int mIdx = tid >> 4;          // rows {mIdx*4..+3} U {64+mIdx*4..+3}

    const int ldd = tid & 15;           // d within BK chunk for tile loads
    const int ldr = tid >> 4;           // base row for tile loads (0..15)

    if (tid < BM) sh_x2[tid] = g_x2[bm + tid];
    __syncthreads();

    float minV[8];
    int   minI[8];
    #pragma unroll
    for (int i = 0; i < 8; ++i) { minV[i] = INFINITY; minI[i] = 0; }

    const float* aG = res_in + (size_t)bm * D_DIM;

    for (int nt = 0; nt < NT_TILES; ++nt) {
        const float* bG = emb + (size_t)(quarter * QN + nt * BN) * D_DIM;

        unsigned long long acc2[8][4];
        #pragma unroll
        for (int i = 0; i < 8; ++i)
            #pragma unroll
            for (int j = 0; j < 4; ++j) acc2[i][j] = 0ull;

        float ra[8], rb[8];
        // prologue: fetch + store chunk 0
        #pragma unroll
        for (int i = 0; i < 8; ++i) {
            int r = ldr + 16 * i;
            ra[i] = aG[(size_t)r * D_DIM + ldd];
            rb[i] = bG[(size_t)r * D_DIM + ldd];
        }
        #pragma unroll
        for (int i = 0; i < 8; ++i) {
            int r = ldr + 16 * i;
            As[0][ldd][r] = ra[i];
            Bs[0][ldd][r] = rb[i];
        }
        __syncthreads();

        #pragma unroll 2
        for (int c = 0; c < NCHUNK; ++c) {
            const int cur = c & 1;
            if (c < NCHUNK - 1) {
                int dc = (c + 1) * BK;
                #pragma unroll
                for (int i = 0; i < 8; ++i) {
                    int r = ldr + 16 * i;
                    ra[i] = aG[(size_t)r * D_DIM + dc + ldd];
                    rb[i] = bG[(size_t)r * D_DIM + dc + ldd];
                }
            }
            #pragma unroll 8
            for (int kk = 0; kk < BK; ++kk) {
                const float4 a0 = *(const float4*)(&As[cur][kk][mIdx * 4]);
                const float4 a1 = *(const float4*)(&As[cur][kk][64 + mIdx * 4]);
                const ulonglong2 b0 = *(const ulonglong2*)(&Bs[cur][kk][nIdx * 4]);
                const ulonglong2 b1 = *(const ulonglong2*)(&Bs[cur][kk][64 + nIdx * 4]);
                unsigned long long aD[8];
                PACK_DUP(aD[0], a0.x); PACK_DUP(aD[1], a0.y);
                PACK_DUP(aD[2], a0.z); PACK_DUP(aD[3], a0.w);
                PACK_DUP(aD[4], a1.x); PACK_DUP(aD[5], a1.y);
                PACK_DUP(aD[6], a1.z); PACK_DUP(aD[7], a1.w);
                const unsigned long long bP[4] = { b0.x, b0.y, b1.x, b1.y };
                #pragma unroll
                for (int i = 0; i < 8; ++i)
                    #pragma unroll
                    for (int j = 0; j < 4; ++j)
                        FMA2(acc2[i][j], aD[i], bP[j]);
            }
            if (c < NCHUNK - 1) {
                const int nxt = (c + 1) & 1;
                #pragma unroll
                for (int i = 0; i < 8; ++i) {
                    int r = ldr + 16 * i;
                    As[nxt][ldd][r] = ra[i];
                    Bs[nxt][ldd][r] = rb[i];
                }
            }
            __syncthreads();
        }

        // epilogue: S = fl(fl(x2 + e2[k]) - 2*dot); running argmin, ascending k
        #pragma unroll
        for (int j = 0; j < 4; ++j) {
            int c0 = (j < 2) ? (nIdx * 4 + 2 * j) : (64 + nIdx * 4 + 2 * (j - 2));
            int g0 = quarter * QN + nt * BN + c0;
            float ek0 = __ldg(&e2[g0]);
            float ek1 = __ldg(&e2[g0 + 1]);
            #pragma unroll
            for (int i = 0; i < 8; ++i) {
                int r = (i < 4) ? (mIdx * 4 + i) : (64 + mIdx * 4 + (i - 4));
                float x2r = sh_x2[r];
                float dlo, dhi;
                UNPACK2(dlo, dhi, acc2[i][j]);
                float A0 = __fadd_rn(x2r, ek0);
                float s0 = __fmaf_rn(-2.0f, dlo, A0);
                if (s0 < minV[i]) { minV[i] = s0; minI[i] = g0; }
                float A1 = __fadd_rn(x2r, ek1);
                float s1 = __fmaf_rn(-2.0f, dhi, A1);
                if (s1 < minV[i]) { minV[i] = s1; minI[i] = g0 + 1; }
            }
        }
    }

    // cross-thread argmin reduction (16 candidates per row), lexicographic
    __syncthreads();
    #pragma unroll
    for (int i = 0; i < 8; ++i) {
        int r = (i < 4) ? (mIdx * 4 + i) : (64 + mIdx * 4 + (i - 4));
        redV[r][nIdx] = minV[i];
        redI[r][nIdx] = minI[i];
    }
    __syncthreads();

    if (tid < BM) {
        float bv = redV[tid][0];
        int   bi = redI[tid][0];
        #pragma unroll
        for (int j = 1; j < 16; ++j) {
            float v = redV[tid][j];
            int  ix = redI[tid][j];
            if (v < bv || (v == bv && ix < bi)) { bv = v; bi = ix; }
        }
        g_bv[quarter * B_ROWS + bm + tid] = bv;
        g_bi[quarter * B_ROWS + bm + tid] = bi;
    }
}

// ---------------------------------------------------------------------------
// Combine per-quarter winners (ascending quarter order = global first-
// occurrence tie-break), write codes, update residual + qsum, and compute
// next level's x2. Block = 32 rows, 8 threads per row.
// ---------------------------------------------------------------------------
__global__ void combine_kernel(const float* __restrict__ residual,
                               const float* __restrict__ codebooks,
                               float* __restrict__ quant,
                               float* __restrict__ codes_out,
                               int level)
{
    __shared__ int sh_idx[32];

    const float* res_in = (level == 0) ? residual : g_res;
    const float* emb = codebooks + (size_t)level * K_CODES * D_DIM;

    const int t = threadIdx.x;
    const int row0 = blockIdx.x * 32;

    if (t < 32) {
        int row = row0 + t;
        float bv = g_bv[row];
        int   bi = g_bi[row];
        #pragma unroll
        for (int q = 1; q < NQ; ++q) {
            float v = g_bv[q * B_ROWS + row];
            int   i = g_bi[q * B_ROWS + row];
            // quarters ascend in index range; strict < keeps first occurrence
            if (v < bv) { bv = v; bi = i; }
        }
        sh_idx[t] = bi;
        codes_out[(size_t)row * L_LVL + level] = (float)bi;
    }
    __syncthreads();

    const int rl = t >> 3, lane8 = t & 7;
    const int row = row0 + rl;
    const int q = sh_idx[rl];
    const float4* rin = (const float4*)(res_in + (size_t)row * D_DIM);
    const float4* ev  = (const float4*)(emb + (size_t)q * D_DIM);
    float4* ro = (float4*)(g_res + (size_t)row * D_DIM);
    float4* qo = (float4*)(quant + (size_t)row * D_DIM);

    double s = 0.0;
    #pragma unroll
    for (int j = 0; j < 8; ++j) {
        int i4 = lane8 + 8 * j;
        float4 a = rin[i4], e = ev[i4];
        if (level < L_LVL - 1) {
            float4 nr = make_float4(__fadd_rn(a.x, -e.x), __fadd_rn(a.y, -e.y),
                                    __fadd_rn(a.z, -e.z), __fadd_rn(a.w, -e.w));
            ro[i4] = nr;
            s += (double)nr.x * nr.x + (double)nr.y * nr.y
               + (double)nr.z * nr.z + (double)nr.w * nr.w;
        }
        if (level == 0) {
            qo[i4] = e;                      // qsum = fl(0 + q) = q
        } else {
            float4 p = qo[i4];
            qo[i4] = make_float4(__fadd_rn(p.x, e.x), __fadd_rn(p.y, e.y),
                                 __fadd_rn(p.z, e.z), __fadd_rn(p.w, e.w));
        }
    }
    if (level < L_LVL - 1) {
        s += __shfl_xor_sync(0xffffffffu, s, 4);
        s += __shfl_xor_sync(0xffffffffu, s, 2);
        s += __shfl_xor_sync(0xffffffffu, s, 1);
        if (lane8 == 0) g_x2[row] = (float)s;
    }
}

// ---------------------------------------------------------------------------
extern "C" void kernel_launch(void* const* d_in, const int* in_sizes, int n_in,
                              void* d_out, int out_size)
{
    const float* residual  = (const float*)d_in[0];   // [B, D] float32
    const float* codebooks = (const float*)d_in[1];   // [L, K, D] float32
    float* out   = (float*)d_out;
    float* quant = out;                               // [B, D]
    float* codes = out + (size_t)B_ROWS * D_DIM;      // [B, L] as float

    e2_kernel<<<(L_LVL * K_CODES * 32 + 255) / 256, 256>>>(codebooks);
    x2_kernel<<<B_ROWS / 32, 256>>>(residual);

    for (int l = 0; l < L_LVL; ++l) {
        rq_level_kernel<<<NROWTILES * NQ, NTHREADS>>>(residual, codebooks, l);
        combine_kernel<<<B_ROWS / 32, 256>>>(residual, codebooks, quant, codes, l);
    }
}